// round 6
// baseline (speedup 1.0000x reference)
#include <cuda_runtime.h>

#define NN 100000
#define NE 1600000
#define CH 128

// ---------------- scratch (static device arrays; no allocation) ----------------
__device__ int   g_deg[NN];          // in-degree + 1 (self loop)
__device__ int   g_cur[NN];          // fill cursors
__device__ int   g_off[NN + 1];      // CSR row offsets (real edges only)
__device__ float g_dis[NN];          // deg^{-1/2}
__device__ int   g_csrc[NE];         // CSR src per dst
__device__ float g_cw[NE];           // edge weight dis[src]*dis[dst]
__device__ __align__(16) float g_bufA[NN * CH];
__device__ __align__(16) float g_bufB[NN * CH];

// ---------------- degree init / count ----------------
__global__ void k_init() {
    int i = blockIdx.x * blockDim.x + threadIdx.x;
    if (i < NN) { g_deg[i] = 1; g_cur[i] = 0; }
}

__global__ void k_count(const int* __restrict__ dst) {
    int i = blockIdx.x * blockDim.x + threadIdx.x;
    if (i < NE) atomicAdd(&g_deg[dst[i]], 1);
}

// ---------------- single-block scan: offsets + dis ----------------
__global__ void k_scan() {
    const int T = 1024;
    int tid = threadIdx.x;
    const int per = (NN + T - 1) / T;
    int beg = tid * per;
    int end = beg + per; if (end > NN) end = NN;
    if (beg > NN) beg = NN;

    int s = 0;
    for (int i = beg; i < end; i++) {
        int d = g_deg[i];
        g_dis[i] = rsqrtf((float)d);
        s += d - 1;                      // real in-degree
    }
    __shared__ int sh[1024];
    sh[tid] = s;
    __syncthreads();
    // Hillis-Steele inclusive scan
    for (int off = 1; off < T; off <<= 1) {
        int v = (tid >= off) ? sh[tid - off] : 0;
        __syncthreads();
        sh[tid] += v;
        __syncthreads();
    }
    int run = (tid == 0) ? 0 : sh[tid - 1];
    for (int i = beg; i < end; i++) {
        g_off[i] = run;
        run += g_deg[i] - 1;
    }
    if (tid == 0) g_off[NN] = sh[T - 1];
}

// ---------------- CSR fill ----------------
__global__ void k_fill(const int* __restrict__ src, const int* __restrict__ dst) {
    int i = blockIdx.x * blockDim.x + threadIdx.x;
    if (i >= NE) return;
    int s = src[i], d = dst[i];
    int pos = g_off[d] + atomicAdd(&g_cur[d], 1);
    g_csrc[pos] = s;
    g_cw[pos]   = g_dis[s] * g_dis[d];
}

// ---------------- SGEMM: C[M,128] = A[M,128] @ W[128,128] ----------------
// 128x128 tile per CTA, 8x8 per thread, BK=8, 256 threads.
__global__ __launch_bounds__(256) void k_gemm(const float* __restrict__ A,
                                              const float* __restrict__ W,
                                              float* __restrict__ C, int M) {
    __shared__ float As[8][128];
    __shared__ float Bs[8][128];
    int tid = threadIdx.x;
    int block_row = blockIdx.x * 128;

    int tr = tid >> 4;       // 0..15
    int tc = tid & 15;       // 0..15

    float acc[8][8];
#pragma unroll
    for (int i = 0; i < 8; i++)
#pragma unroll
        for (int j = 0; j < 8; j++) acc[i][j] = 0.f;

    int arow  = tid >> 1;            // 0..127
    int acol4 = (tid & 1) * 4;       // 0 or 4
    int brow  = tid >> 5;            // 0..7
    int bcol4 = (tid & 31) * 4;      // 0..124

#pragma unroll 1
    for (int kk = 0; kk < 128; kk += 8) {
        float4 av = make_float4(0.f, 0.f, 0.f, 0.f);
        int gr = block_row + arow;
        if (gr < M)
            av = *(const float4*)(A + (size_t)gr * 128 + kk + acol4);
        As[acol4 + 0][arow] = av.x;
        As[acol4 + 1][arow] = av.y;
        As[acol4 + 2][arow] = av.z;
        As[acol4 + 3][arow] = av.w;

        float4 bv = *(const float4*)(W + (size_t)(kk + brow) * 128 + bcol4);
        *(float4*)&Bs[brow][bcol4] = bv;
        __syncthreads();

#pragma unroll
        for (int k = 0; k < 8; k++) {
            float4 rm0 = *(const float4*)&As[k][tr * 8];
            float4 rm1 = *(const float4*)&As[k][tr * 8 + 4];
            float4 rn0 = *(const float4*)&Bs[k][tc * 8];
            float4 rn1 = *(const float4*)&Bs[k][tc * 8 + 4];
            float rm[8] = {rm0.x, rm0.y, rm0.z, rm0.w, rm1.x, rm1.y, rm1.z, rm1.w};
            float rn[8] = {rn0.x, rn0.y, rn0.z, rn0.w, rn1.x, rn1.y, rn1.z, rn1.w};
#pragma unroll
            for (int i = 0; i < 8; i++)
#pragma unroll
                for (int j = 0; j < 8; j++)
                    acc[i][j] += rm[i] * rn[j];
        }
        __syncthreads();
    }

#pragma unroll
    for (int i = 0; i < 8; i++) {
        int gr = block_row + tr * 8 + i;
        if (gr < M) {
            float4* cp = (float4*)(C + (size_t)gr * 128 + tc * 8);
            cp[0] = make_float4(acc[i][0], acc[i][1], acc[i][2], acc[i][3]);
            cp[1] = make_float4(acc[i][4], acc[i][5], acc[i][6], acc[i][7]);
        }
    }
}

// ---------------- SpMM: out[n] = bias + dis[n]^2*h[n] + sum_e w_e*h[src_e], optional relu ----
// one warp per node; each lane owns 4 channels (float4)
__global__ __launch_bounds__(256) void k_spmm(const float* __restrict__ h,
                                              const float* __restrict__ bias,
                                              float* __restrict__ out, int do_relu) {
    int node = (blockIdx.x * blockDim.x + threadIdx.x) >> 5;
    if (node >= NN) return;
    int lane = threadIdx.x & 31;

    const float4* h4 = (const float4*)h;
    float dsi = g_dis[node];
    float sw  = dsi * dsi;
    float4 hv = h4[node * 32 + lane];
    float ax = hv.x * sw, ay = hv.y * sw, az = hv.z * sw, aw = hv.w * sw;
    float bx = 0.f, by = 0.f, bz = 0.f, bw = 0.f;

    int e   = g_off[node];
    int end = g_off[node + 1];

    // 2-way unrolled gather-accumulate (doubles MLP on the random L2 gathers)
    for (; e + 1 < end; e += 2) {
        int   s0 = g_csrc[e],     s1 = g_csrc[e + 1];
        float w0 = g_cw[e],       w1 = g_cw[e + 1];
        float4 v0 = h4[s0 * 32 + lane];
        float4 v1 = h4[s1 * 32 + lane];
        ax += w0 * v0.x; ay += w0 * v0.y; az += w0 * v0.z; aw += w0 * v0.w;
        bx += w1 * v1.x; by += w1 * v1.y; bz += w1 * v1.z; bw += w1 * v1.w;
    }
    if (e < end) {
        int   s0 = g_csrc[e];
        float w0 = g_cw[e];
        float4 v0 = h4[s0 * 32 + lane];
        ax += w0 * v0.x; ay += w0 * v0.y; az += w0 * v0.z; aw += w0 * v0.w;
    }

    float4 bb = ((const float4*)bias)[lane];
    ax += bx + bb.x; ay += by + bb.y; az += bz + bb.z; aw += bw + bb.w;
    if (do_relu) {
        ax = fmaxf(ax, 0.f); ay = fmaxf(ay, 0.f);
        az = fmaxf(az, 0.f); aw = fmaxf(aw, 0.f);
    }
    ((float4*)out)[node * 32 + lane] = make_float4(ax, ay, az, aw);
}

// ---------------- launch ----------------
extern "C" void kernel_launch(void* const* d_in, const int* in_sizes, int n_in,
                              void* d_out, int out_size) {
    // metadata order: x, last_update, edge_index, t, msg, W1, b1, W2, b2
    const float* x  = (const float*)d_in[0];
    const int*   ei = (const int*)d_in[2];
    const float* W1 = (const float*)d_in[5];
    const float* b1 = (const float*)d_in[6];
    const float* W2 = (const float*)d_in[7];
    const float* b2 = (const float*)d_in[8];
    float* out = (float*)d_out;

    const int* src = ei;        // edge_index[0]
    const int* dst = ei + NE;   // edge_index[1]

    float *bufA, *bufB;
    cudaGetSymbolAddress((void**)&bufA, g_bufA);
    cudaGetSymbolAddress((void**)&bufB, g_bufB);

    // CSR build
    k_init <<<(NN + 255) / 256, 256>>>();
    k_count<<<(NE + 255) / 256, 256>>>(dst);
    k_scan <<<1, 1024>>>();
    k_fill <<<(NE + 255) / 256, 256>>>(src, dst);

    // layer 1: h = x@W1; agg+b1+relu
    k_gemm<<<(NN + 127) / 128, 256>>>(x, W1, bufA, NN);
    k_spmm<<<(NN * 32 + 255) / 256, 256>>>(bufA, b1, bufB, 1);

    // layer 2: h = agg1@W2; agg+b2
    k_gemm<<<(NN + 127) / 128, 256>>>(bufB, W2, bufA, NN);
    k_spmm<<<(NN * 32 + 255) / 256, 256>>>(bufA, b2, out, 0);
}

// round 7
// speedup vs baseline: 1.0124x; 1.0124x over previous
#include <cuda_runtime.h>

#define NN 100000
#define NE 1600000
#define CH 128

typedef unsigned long long ull;

// ---------------- scratch (static device arrays; no allocation) ----------------
__device__ int   g_deg[NN];          // in-degree + 1 (self loop)
__device__ int   g_cur[NN];          // fill cursors
__device__ int   g_off[NN + 1];      // CSR row offsets (real edges only)
__device__ float g_dis[NN];          // deg^{-1/2}
__device__ int   g_csrc[NE];         // CSR src per dst
__device__ float g_cw[NE];           // edge weight dis[src]*dis[dst]
__device__ __align__(16) float g_bufA[NN * CH];
__device__ __align__(16) float g_bufB[NN * CH];

// ---------------- packed f32x2 helpers (Blackwell FFMA2 path) ----------------
__device__ __forceinline__ ull pack_dup(float a) {
    ull r;
    asm("mov.b64 %0, {%1, %1};" : "=l"(r) : "f"(a));
    return r;
}
__device__ __forceinline__ void fma2(ull& d, ull a, ull b) {
    asm("fma.rn.f32x2 %0, %1, %2, %0;" : "+l"(d) : "l"(a), "l"(b));
}
__device__ __forceinline__ float2 unpack2(ull v) {
    float2 r;
    asm("mov.b64 {%0, %1}, %2;" : "=f"(r.x), "=f"(r.y) : "l"(v));
    return r;
}

// ---------------- degree init / count ----------------
__global__ void k_init() {
    int i = blockIdx.x * blockDim.x + threadIdx.x;
    if (i < NN) { g_deg[i] = 1; g_cur[i] = 0; }
}

__global__ void k_count(const int* __restrict__ dst) {
    int i = blockIdx.x * blockDim.x + threadIdx.x;
    if (i < NE) atomicAdd(&g_deg[dst[i]], 1);
}

// ---------------- single-block scan: offsets + dis ----------------
__global__ void k_scan() {
    const int T = 1024;
    int tid = threadIdx.x;
    const int per = (NN + T - 1) / T;
    int beg = tid * per;
    int end = beg + per; if (end > NN) end = NN;
    if (beg > NN) beg = NN;

    int s = 0;
    for (int i = beg; i < end; i++) {
        int d = g_deg[i];
        g_dis[i] = rsqrtf((float)d);
        s += d - 1;                      // real in-degree
    }
    __shared__ int sh[1024];
    sh[tid] = s;
    __syncthreads();
    for (int off = 1; off < T; off <<= 1) {
        int v = (tid >= off) ? sh[tid - off] : 0;
        __syncthreads();
        sh[tid] += v;
        __syncthreads();
    }
    int run = (tid == 0) ? 0 : sh[tid - 1];
    for (int i = beg; i < end; i++) {
        g_off[i] = run;
        run += g_deg[i] - 1;
    }
    if (tid == 0) g_off[NN] = sh[T - 1];
}

// ---------------- CSR fill ----------------
__global__ void k_fill(const int* __restrict__ src, const int* __restrict__ dst) {
    int i = blockIdx.x * blockDim.x + threadIdx.x;
    if (i >= NE) return;
    int s = src[i], d = dst[i];
    int pos = g_off[d] + atomicAdd(&g_cur[d], 1);
    g_csrc[pos] = s;
    g_cw[pos]   = g_dis[s] * g_dis[d];
}

// ---------------- SGEMM: C[M,128] = A[M,128] @ W[128,128] ----------------
// 128x128 tile per CTA, 8 rows x 4 col-pairs per thread via fma.rn.f32x2,
// BK=8, 256 threads.
__global__ __launch_bounds__(256) void k_gemm(const float* __restrict__ A,
                                              const float* __restrict__ W,
                                              float* __restrict__ C, int M) {
    __shared__ float As[8][128];
    __shared__ float Bs[8][128];
    int tid = threadIdx.x;
    int block_row = blockIdx.x * 128;

    int tr = tid >> 4;       // 0..15 (row group of 8)
    int tc = tid & 15;       // 0..15 (col group of 8 = 4 pairs)

    ull acc[8][4];
#pragma unroll
    for (int i = 0; i < 8; i++)
#pragma unroll
        for (int j = 0; j < 4; j++) acc[i][j] = 0ull;  // bits of {0.f,0.f}

    int arow  = tid >> 1;            // 0..127
    int acol4 = (tid & 1) * 4;       // 0 or 4
    int brow  = tid >> 5;            // 0..7
    int bcol4 = (tid & 31) * 4;      // 0..124

#pragma unroll 1
    for (int kk = 0; kk < 128; kk += 8) {
        float4 av = make_float4(0.f, 0.f, 0.f, 0.f);
        int gr = block_row + arow;
        if (gr < M)
            av = *(const float4*)(A + (size_t)gr * 128 + kk + acol4);
        As[acol4 + 0][arow] = av.x;
        As[acol4 + 1][arow] = av.y;
        As[acol4 + 2][arow] = av.z;
        As[acol4 + 3][arow] = av.w;

        float4 bv = *(const float4*)(W + (size_t)(kk + brow) * 128 + bcol4);
        *(float4*)&Bs[brow][bcol4] = bv;
        __syncthreads();

#pragma unroll
        for (int k = 0; k < 8; k++) {
            float4 rm0 = *(const float4*)&As[k][tr * 8];
            float4 rm1 = *(const float4*)&As[k][tr * 8 + 4];
            ull rmd[8];
            rmd[0] = pack_dup(rm0.x); rmd[1] = pack_dup(rm0.y);
            rmd[2] = pack_dup(rm0.z); rmd[3] = pack_dup(rm0.w);
            rmd[4] = pack_dup(rm1.x); rmd[5] = pack_dup(rm1.y);
            rmd[6] = pack_dup(rm1.z); rmd[7] = pack_dup(rm1.w);

            const ull* bp = (const ull*)&Bs[k][tc * 8];
            ull rn0 = bp[0], rn1 = bp[1], rn2 = bp[2], rn3 = bp[3];

#pragma unroll
            for (int i = 0; i < 8; i++) {
                fma2(acc[i][0], rmd[i], rn0);
                fma2(acc[i][1], rmd[i], rn1);
                fma2(acc[i][2], rmd[i], rn2);
                fma2(acc[i][3], rmd[i], rn3);
            }
        }
        __syncthreads();
    }

#pragma unroll
    for (int i = 0; i < 8; i++) {
        int gr = block_row + tr * 8 + i;
        if (gr < M) {
            float2 p0 = unpack2(acc[i][0]);
            float2 p1 = unpack2(acc[i][1]);
            float2 p2 = unpack2(acc[i][2]);
            float2 p3 = unpack2(acc[i][3]);
            float4* cp = (float4*)(C + (size_t)gr * 128 + tc * 8);
            cp[0] = make_float4(p0.x, p0.y, p1.x, p1.y);
            cp[1] = make_float4(p2.x, p2.y, p3.x, p3.y);
        }
    }
}

// ---------------- SpMM: out[n] = bias + dis[n]^2*h[n] + sum_e w_e*h[src_e], optional relu ----
// one warp per node; each lane owns 4 channels (float4); 4-deep gather unroll.
__global__ __launch_bounds__(256) void k_spmm(const float* __restrict__ h,
                                              const float* __restrict__ bias,
                                              float* __restrict__ out, int do_relu) {
    int node = (blockIdx.x * blockDim.x + threadIdx.x) >> 5;
    if (node >= NN) return;
    int lane = threadIdx.x & 31;

    const float4* h4 = (const float4*)h;
    float dsi = g_dis[node];
    float sw  = dsi * dsi;
    float4 hv = h4[node * 32 + lane];
    float ax = hv.x * sw, ay = hv.y * sw, az = hv.z * sw, aw = hv.w * sw;
    float bx = 0.f, by = 0.f, bz = 0.f, bw = 0.f;

    int e   = g_off[node];
    int end = g_off[node + 1];

    // 4-deep unrolled gather-accumulate: 4 independent 512B row loads in flight,
    // two accumulator chains to keep FMA dependencies short.
    for (; e + 3 < end; e += 4) {
        int   s0 = g_csrc[e],     s1 = g_csrc[e + 1];
        int   s2 = g_csrc[e + 2], s3 = g_csrc[e + 3];
        float w0 = g_cw[e],       w1 = g_cw[e + 1];
        float w2 = g_cw[e + 2],   w3 = g_cw[e + 3];
        float4 v0 = h4[s0 * 32 + lane];
        float4 v1 = h4[s1 * 32 + lane];
        float4 v2 = h4[s2 * 32 + lane];
        float4 v3 = h4[s3 * 32 + lane];
        ax += w0 * v0.x; ay += w0 * v0.y; az += w0 * v0.z; aw += w0 * v0.w;
        bx += w1 * v1.x; by += w1 * v1.y; bz += w1 * v1.z; bw += w1 * v1.w;
        ax += w2 * v2.x; ay += w2 * v2.y; az += w2 * v2.z; aw += w2 * v2.w;
        bx += w3 * v3.x; by += w3 * v3.y; bz += w3 * v3.z; bw += w3 * v3.w;
    }
    for (; e < end; e++) {
        int   s0 = g_csrc[e];
        float w0 = g_cw[e];
        float4 v0 = h4[s0 * 32 + lane];
        ax += w0 * v0.x; ay += w0 * v0.y; az += w0 * v0.z; aw += w0 * v0.w;
    }

    float4 bb = ((const float4*)bias)[lane];
    ax += bx + bb.x; ay += by + bb.y; az += bz + bb.z; aw += bw + bb.w;
    if (do_relu) {
        ax = fmaxf(ax, 0.f); ay = fmaxf(ay, 0.f);
        az = fmaxf(az, 0.f); aw = fmaxf(aw, 0.f);
    }
    ((float4*)out)[node * 32 + lane] = make_float4(ax, ay, az, aw);
}

// ---------------- launch ----------------
extern "C" void kernel_launch(void* const* d_in, const int* in_sizes, int n_in,
                              void* d_out, int out_size) {
    // metadata order: x, last_update, edge_index, t, msg, W1, b1, W2, b2
    const float* x  = (const float*)d_in[0];
    const int*   ei = (const int*)d_in[2];
    const float* W1 = (const float*)d_in[5];
    const float* b1 = (const float*)d_in[6];
    const float* W2 = (const float*)d_in[7];
    const float* b2 = (const float*)d_in[8];
    float* out = (float*)d_out;

    const int* src = ei;        // edge_index[0]
    const int* dst = ei + NE;   // edge_index[1]

    float *bufA, *bufB;
    cudaGetSymbolAddress((void**)&bufA, g_bufA);
    cudaGetSymbolAddress((void**)&bufB, g_bufB);

    // CSR build
    k_init <<<(NN + 255) / 256, 256>>>();
    k_count<<<(NE + 255) / 256, 256>>>(dst);
    k_scan <<<1, 1024>>>();
    k_fill <<<(NE + 255) / 256, 256>>>(src, dst);

    // layer 1: h = x@W1; agg+b1+relu
    k_gemm<<<(NN + 127) / 128, 256>>>(x, W1, bufA, NN);
    k_spmm<<<(NN * 32 + 255) / 256, 256>>>(bufA, b1, bufB, 1);

    // layer 2: h = agg1@W2; agg+b2
    k_gemm<<<(NN + 127) / 128, 256>>>(bufB, W2, bufA, NN);
    k_spmm<<<(NN * 32 + 255) / 256, 256>>>(bufA, b2, out, 0);
}

// round 8
// speedup vs baseline: 1.4715x; 1.4536x over previous
#include <cuda_runtime.h>

#define NN 100000
#define NE 1600000
#define CH 128
#define SCAN_CHUNK 512
#define SCAN_NB ((NN + SCAN_CHUNK - 1) / SCAN_CHUNK)   // 196

typedef unsigned long long ull;

// ---------------- scratch (static device arrays; no allocation) ----------------
__device__ int   g_deg[NN];          // in-degree + 1 (self loop)
__device__ int   g_cur[NN];          // fill cursors
__device__ int   g_off[NN + 1];      // CSR row offsets (real edges only)
__device__ float g_dis[NN];          // deg^{-1/2}
__device__ int   g_bsum[SCAN_NB];    // per-block sums
__device__ int   g_bbase[SCAN_NB];   // per-block exclusive bases
__device__ int   g_csrc[NE];         // CSR src per dst
__device__ float g_cw[NE];           // edge weight dis[src]*dis[dst]
__device__ __align__(16) float g_bufA[NN * CH];
__device__ __align__(16) float g_bufB[NN * CH];

// ---------------- packed f32x2 helpers (Blackwell FFMA2 path) ----------------
__device__ __forceinline__ ull pack_dup(float a) {
    ull r;
    asm("mov.b64 %0, {%1, %1};" : "=l"(r) : "f"(a));
    return r;
}
__device__ __forceinline__ void fma2(ull& d, ull a, ull b) {
    asm("fma.rn.f32x2 %0, %1, %2, %0;" : "+l"(d) : "l"(a), "l"(b));
}
__device__ __forceinline__ float2 unpack2(ull v) {
    float2 r;
    asm("mov.b64 {%0, %1}, %2;" : "=f"(r.x), "=f"(r.y) : "l"(v));
    return r;
}

// ---------------- degree init / count ----------------
__global__ void k_init() {
    int i = blockIdx.x * blockDim.x + threadIdx.x;
    if (i < NN) { g_deg[i] = 1; g_cur[i] = 0; }
}

__global__ void k_count(const int* __restrict__ dst) {
    int i = blockIdx.x * blockDim.x + threadIdx.x;
    if (i < NE) atomicAdd(&g_deg[dst[i]], 1);
}

// ---------------- hierarchical scan ----------------
// Phase A: per-block sums of (deg-1); also compute dis = rsqrt(deg).
__global__ __launch_bounds__(256) void k_scanA() {
    __shared__ int sh[256];
    int tid = threadIdx.x;
    int base = blockIdx.x * SCAN_CHUNK;
    int s = 0;
#pragma unroll
    for (int j = 0; j < 2; j++) {
        int i = base + tid * 2 + j;
        if (i < NN) {
            int d = g_deg[i];
            g_dis[i] = rsqrtf((float)d);
            s += d - 1;
        }
    }
    sh[tid] = s;
    __syncthreads();
#pragma unroll
    for (int off = 128; off > 0; off >>= 1) {
        if (tid < off) sh[tid] += sh[tid + off];
        __syncthreads();
    }
    if (tid == 0) g_bsum[blockIdx.x] = sh[0];
}

// Phase B: single block scans the block sums (SCAN_NB <= 256).
__global__ __launch_bounds__(256) void k_scanB() {
    __shared__ int sh[256];
    int tid = threadIdx.x;
    int v = (tid < SCAN_NB) ? g_bsum[tid] : 0;
    sh[tid] = v;
    __syncthreads();
#pragma unroll
    for (int off = 1; off < 256; off <<= 1) {
        int t = (tid >= off) ? sh[tid - off] : 0;
        __syncthreads();
        sh[tid] += t;
        __syncthreads();
    }
    if (tid < SCAN_NB) g_bbase[tid] = sh[tid] - v;   // exclusive
    if (tid == 255) g_off[NN] = sh[255];             // total real edges
}

// Phase C: per-block exclusive scan + base -> g_off.
__global__ __launch_bounds__(256) void k_scanC() {
    __shared__ int sh[256];
    int tid = threadIdx.x;
    int base = blockIdx.x * SCAN_CHUNK;
    int i0 = base + tid * 2;
    int d0 = (i0 < NN)     ? g_deg[i0] - 1     : 0;
    int d1 = (i0 + 1 < NN) ? g_deg[i0 + 1] - 1 : 0;
    int pair = d0 + d1;
    sh[tid] = pair;
    __syncthreads();
#pragma unroll
    for (int off = 1; off < 256; off <<= 1) {
        int t = (tid >= off) ? sh[tid - off] : 0;
        __syncthreads();
        sh[tid] += t;
        __syncthreads();
    }
    int excl = g_bbase[blockIdx.x] + sh[tid] - pair;
    if (i0 < NN)     g_off[i0]     = excl;
    if (i0 + 1 < NN) g_off[i0 + 1] = excl + d0;
}

// ---------------- CSR fill ----------------
__global__ void k_fill(const int* __restrict__ src, const int* __restrict__ dst) {
    int i = blockIdx.x * blockDim.x + threadIdx.x;
    if (i >= NE) return;
    int s = src[i], d = dst[i];
    int pos = g_off[d] + atomicAdd(&g_cur[d], 1);
    g_csrc[pos] = s;
    g_cw[pos]   = g_dis[s] * g_dis[d];
}

// ---------------- SGEMM: C[M,128] = A[M,128] @ W[128,128] ----------------
// 128x128 tile per CTA, FFMA2 accumulators, BK=8, 256 threads.
// Bs uses a skewed layout (physical col = c + 2*(c>>3), row stride 160 floats)
// so the 8-float-stride per-lane reads hit 16 distinct banks (conflict-free).
__global__ __launch_bounds__(256) void k_gemm(const float* __restrict__ A,
                                              const float* __restrict__ W,
                                              float* __restrict__ C, int M) {
    __shared__ float As[8][128];
    __shared__ float Bs[8][160];
    int tid = threadIdx.x;
    int block_row = blockIdx.x * 128;

    int tr = tid >> 4;       // 0..15 (row group of 8)
    int tc = tid & 15;       // 0..15 (col group of 8 = 4 pairs)

    ull acc[8][4];
#pragma unroll
    for (int i = 0; i < 8; i++)
#pragma unroll
        for (int j = 0; j < 4; j++) acc[i][j] = 0ull;

    int arow  = tid >> 1;            // 0..127
    int acol4 = (tid & 1) * 4;       // 0 or 4
    int brow  = tid >> 5;            // 0..7
    int bcol4 = (tid & 31) * 4;      // logical col 0..124 (mult of 4)
    int bphys = bcol4 + 2 * (bcol4 >> 3);  // skewed physical col (always even)

#pragma unroll 1
    for (int kk = 0; kk < 128; kk += 8) {
        float4 av = make_float4(0.f, 0.f, 0.f, 0.f);
        int gr = block_row + arow;
        if (gr < M)
            av = *(const float4*)(A + (size_t)gr * 128 + kk + acol4);
        As[acol4 + 0][arow] = av.x;
        As[acol4 + 1][arow] = av.y;
        As[acol4 + 2][arow] = av.z;
        As[acol4 + 3][arow] = av.w;

        float4 bv = *(const float4*)(W + (size_t)(kk + brow) * 128 + bcol4);
        // c0..c0+3 lie within one 8-group -> physically contiguous; p even -> float2 ok
        *(float2*)&Bs[brow][bphys]     = make_float2(bv.x, bv.y);
        *(float2*)&Bs[brow][bphys + 2] = make_float2(bv.z, bv.w);
        __syncthreads();

#pragma unroll
        for (int k = 0; k < 8; k++) {
            float4 rm0 = *(const float4*)&As[k][tr * 8];
            float4 rm1 = *(const float4*)&As[k][tr * 8 + 4];
            ull rmd[8];
            rmd[0] = pack_dup(rm0.x); rmd[1] = pack_dup(rm0.y);
            rmd[2] = pack_dup(rm0.z); rmd[3] = pack_dup(rm0.w);
            rmd[4] = pack_dup(rm1.x); rmd[5] = pack_dup(rm1.y);
            rmd[6] = pack_dup(rm1.z); rmd[7] = pack_dup(rm1.w);

            const ull* bp = (const ull*)&Bs[k][tc * 10];  // 10 = 8 + 2 skew
            ull rn0 = bp[0], rn1 = bp[1], rn2 = bp[2], rn3 = bp[3];

#pragma unroll
            for (int i = 0; i < 8; i++) {
                fma2(acc[i][0], rmd[i], rn0);
                fma2(acc[i][1], rmd[i], rn1);
                fma2(acc[i][2], rmd[i], rn2);
                fma2(acc[i][3], rmd[i], rn3);
            }
        }
        __syncthreads();
    }

#pragma unroll
    for (int i = 0; i < 8; i++) {
        int gr = block_row + tr * 8 + i;
        if (gr < M) {
            float2 p0 = unpack2(acc[i][0]);
            float2 p1 = unpack2(acc[i][1]);
            float2 p2 = unpack2(acc[i][2]);
            float2 p3 = unpack2(acc[i][3]);
            float4* cp = (float4*)(C + (size_t)gr * 128 + tc * 8);
            cp[0] = make_float4(p0.x, p0.y, p1.x, p1.y);
            cp[1] = make_float4(p2.x, p2.y, p3.x, p3.y);
        }
    }
}

// ---------------- SpMM: out[n] = bias + dis[n]^2*h[n] + sum_e w_e*h[src_e], optional relu ----
__global__ __launch_bounds__(256) void k_spmm(const float* __restrict__ h,
                                              const float* __restrict__ bias,
                                              float* __restrict__ out, int do_relu) {
    int node = (blockIdx.x * blockDim.x + threadIdx.x) >> 5;
    if (node >= NN) return;
    int lane = threadIdx.x & 31;

    const float4* h4 = (const float4*)h;
    float dsi = g_dis[node];
    float sw  = dsi * dsi;
    float4 hv = h4[node * 32 + lane];
    float ax = hv.x * sw, ay = hv.y * sw, az = hv.z * sw, aw = hv.w * sw;
    float bx = 0.f, by = 0.f, bz = 0.f, bw = 0.f;

    int e   = g_off[node];
    int end = g_off[node + 1];

    for (; e + 3 < end; e += 4) {
        int   s0 = g_csrc[e],     s1 = g_csrc[e + 1];
        int   s2 = g_csrc[e + 2], s3 = g_csrc[e + 3];
        float w0 = g_cw[e],       w1 = g_cw[e + 1];
        float w2 = g_cw[e + 2],   w3 = g_cw[e + 3];
        float4 v0 = h4[s0 * 32 + lane];
        float4 v1 = h4[s1 * 32 + lane];
        float4 v2 = h4[s2 * 32 + lane];
        float4 v3 = h4[s3 * 32 + lane];
        ax += w0 * v0.x; ay += w0 * v0.y; az += w0 * v0.z; aw += w0 * v0.w;
        bx += w1 * v1.x; by += w1 * v1.y; bz += w1 * v1.z; bw += w1 * v1.w;
        ax += w2 * v2.x; ay += w2 * v2.y; az += w2 * v2.z; aw += w2 * v2.w;
        bx += w3 * v3.x; by += w3 * v3.y; bz += w3 * v3.z; bw += w3 * v3.w;
    }
    for (; e < end; e++) {
        int   s0 = g_csrc[e];
        float w0 = g_cw[e];
        float4 v0 = h4[s0 * 32 + lane];
        ax += w0 * v0.x; ay += w0 * v0.y; az += w0 * v0.z; aw += w0 * v0.w;
    }

    float4 bb = ((const float4*)bias)[lane];
    ax += bx + bb.x; ay += by + bb.y; az += bz + bb.z; aw += bw + bb.w;
    if (do_relu) {
        ax = fmaxf(ax, 0.f); ay = fmaxf(ay, 0.f);
        az = fmaxf(az, 0.f); aw = fmaxf(aw, 0.f);
    }
    ((float4*)out)[node * 32 + lane] = make_float4(ax, ay, az, aw);
}

// ---------------- launch ----------------
extern "C" void kernel_launch(void* const* d_in, const int* in_sizes, int n_in,
                              void* d_out, int out_size) {
    // metadata order: x, last_update, edge_index, t, msg, W1, b1, W2, b2
    const float* x  = (const float*)d_in[0];
    const int*   ei = (const int*)d_in[2];
    const float* W1 = (const float*)d_in[5];
    const float* b1 = (const float*)d_in[6];
    const float* W2 = (const float*)d_in[7];
    const float* b2 = (const float*)d_in[8];
    float* out = (float*)d_out;

    const int* src = ei;        // edge_index[0]
    const int* dst = ei + NE;   // edge_index[1]

    float *bufA, *bufB;
    cudaGetSymbolAddress((void**)&bufA, g_bufA);
    cudaGetSymbolAddress((void**)&bufB, g_bufB);

    // CSR build
    k_init <<<(NN + 255) / 256, 256>>>();
    k_count<<<(NE + 255) / 256, 256>>>(dst);
    k_scanA<<<SCAN_NB, 256>>>();
    k_scanB<<<1, 256>>>();
    k_scanC<<<SCAN_NB, 256>>>();
    k_fill <<<(NE + 255) / 256, 256>>>(src, dst);

    // layer 1: h = x@W1; agg+b1+relu
    k_gemm<<<(NN + 127) / 128, 256>>>(x, W1, bufA, NN);
    k_spmm<<<(NN * 32 + 255) / 256, 256>>>(bufA, b1, bufB, 1);

    // layer 2: h = agg1@W2; agg+b2
    k_gemm<<<(NN + 127) / 128, 256>>>(bufB, W2, bufA, NN);
    k_spmm<<<(NN * 32 + 255) / 256, 256>>>(bufA, b2, out, 0);
}

// round 9
// speedup vs baseline: 1.7421x; 1.1838x over previous
#include <cuda_runtime.h>
#include <cuda_fp16.h>

#define NN 100000
#define NE 1600000
#define CH 128
#define SCAN_CHUNK 512
#define SCAN_NB ((NN + SCAN_CHUNK - 1) / SCAN_CHUNK)   // 196

typedef unsigned long long ull;

// ---------------- scratch (static device arrays; no allocation) ----------------
__device__ int    g_deg[NN];          // in-degree + 1 (self loop)
__device__ int    g_cur[NN];          // fill cursors
__device__ int    g_off[NN + 1];      // CSR row offsets (real edges only)
__device__ float  g_dis[NN];          // deg^{-1/2}
__device__ int    g_bsum[SCAN_NB];
__device__ int    g_bbase[SCAN_NB];
__device__ int2   g_epack[NE];        // {src, f32-bits weight} per CSR slot
__device__ __align__(16) __half g_h16[NN * CH];   // fp16 feature rows (gather target)
__device__ __align__(16) float  g_agg[NN * CH];   // fp32 layer-1 aggregate

// ---------------- packed f32x2 helpers (Blackwell FFMA2 path) ----------------
__device__ __forceinline__ ull pack_dup(float a) {
    ull r;
    asm("mov.b64 %0, {%1, %1};" : "=l"(r) : "f"(a));
    return r;
}
__device__ __forceinline__ void fma2(ull& d, ull a, ull b) {
    asm("fma.rn.f32x2 %0, %1, %2, %0;" : "+l"(d) : "l"(a), "l"(b));
}
__device__ __forceinline__ float2 unpack2(ull v) {
    float2 r;
    asm("mov.b64 {%0, %1}, %2;" : "=f"(r.x), "=f"(r.y) : "l"(v));
    return r;
}

// ---------------- degree init / count ----------------
__global__ void k_init() {
    int i = blockIdx.x * blockDim.x + threadIdx.x;
    if (i < NN) { g_deg[i] = 1; g_cur[i] = 0; }
}

__global__ void k_count(const int* __restrict__ dst) {
    int i = blockIdx.x * blockDim.x + threadIdx.x;
    if (i < NE) atomicAdd(&g_deg[dst[i]], 1);
}

// ---------------- hierarchical scan ----------------
__global__ __launch_bounds__(256) void k_scanA() {
    __shared__ int sh[256];
    int tid = threadIdx.x;
    int base = blockIdx.x * SCAN_CHUNK;
    int s = 0;
#pragma unroll
    for (int j = 0; j < 2; j++) {
        int i = base + tid * 2 + j;
        if (i < NN) {
            int d = g_deg[i];
            g_dis[i] = rsqrtf((float)d);
            s += d - 1;
        }
    }
    sh[tid] = s;
    __syncthreads();
#pragma unroll
    for (int off = 128; off > 0; off >>= 1) {
        if (tid < off) sh[tid] += sh[tid + off];
        __syncthreads();
    }
    if (tid == 0) g_bsum[blockIdx.x] = sh[0];
}

__global__ __launch_bounds__(256) void k_scanB() {
    __shared__ int sh[256];
    int tid = threadIdx.x;
    int v = (tid < SCAN_NB) ? g_bsum[tid] : 0;
    sh[tid] = v;
    __syncthreads();
#pragma unroll
    for (int off = 1; off < 256; off <<= 1) {
        int t = (tid >= off) ? sh[tid - off] : 0;
        __syncthreads();
        sh[tid] += t;
        __syncthreads();
    }
    if (tid < SCAN_NB) g_bbase[tid] = sh[tid] - v;   // exclusive
    if (tid == 255) g_off[NN] = sh[255];
}

__global__ __launch_bounds__(256) void k_scanC() {
    __shared__ int sh[256];
    int tid = threadIdx.x;
    int base = blockIdx.x * SCAN_CHUNK;
    int i0 = base + tid * 2;
    int d0 = (i0 < NN)     ? g_deg[i0] - 1     : 0;
    int d1 = (i0 + 1 < NN) ? g_deg[i0 + 1] - 1 : 0;
    int pair = d0 + d1;
    sh[tid] = pair;
    __syncthreads();
#pragma unroll
    for (int off = 1; off < 256; off <<= 1) {
        int t = (tid >= off) ? sh[tid - off] : 0;
        __syncthreads();
        sh[tid] += t;
        __syncthreads();
    }
    int excl = g_bbase[blockIdx.x] + sh[tid] - pair;
    if (i0 < NN)     g_off[i0]     = excl;
    if (i0 + 1 < NN) g_off[i0 + 1] = excl + d0;
}

// ---------------- CSR fill (packed edge record, single ST.64) ----------------
__global__ void k_fill(const int* __restrict__ src, const int* __restrict__ dst) {
    int i = blockIdx.x * blockDim.x + threadIdx.x;
    if (i >= NE) return;
    int s = src[i], d = dst[i];
    int pos = g_off[d] + atomicAdd(&g_cur[d], 1);
    float w = g_dis[s] * g_dis[d];
    g_epack[pos] = make_int2(s, __float_as_int(w));
}

// ---------------- SGEMM: C[M,128](fp16) = A[M,128](fp32) @ W[128,128](fp32) --
// 128x128 tile per CTA, FFMA2 accumulators, BK=8, 256 threads, skewed Bs.
__global__ __launch_bounds__(256) void k_gemm(const float* __restrict__ A,
                                              const float* __restrict__ W,
                                              __half* __restrict__ C, int M) {
    __shared__ float As[8][128];
    __shared__ float Bs[8][160];
    int tid = threadIdx.x;
    int block_row = blockIdx.x * 128;

    int tr = tid >> 4;       // 0..15 (row group of 8)
    int tc = tid & 15;       // 0..15 (col group of 8 = 4 pairs)

    ull acc[8][4];
#pragma unroll
    for (int i = 0; i < 8; i++)
#pragma unroll
        for (int j = 0; j < 4; j++) acc[i][j] = 0ull;

    int arow  = tid >> 1;
    int acol4 = (tid & 1) * 4;
    int brow  = tid >> 5;
    int bcol4 = (tid & 31) * 4;
    int bphys = bcol4 + 2 * (bcol4 >> 3);  // skew: always even

#pragma unroll 1
    for (int kk = 0; kk < 128; kk += 8) {
        float4 av = make_float4(0.f, 0.f, 0.f, 0.f);
        int gr = block_row + arow;
        if (gr < M)
            av = *(const float4*)(A + (size_t)gr * 128 + kk + acol4);
        As[acol4 + 0][arow] = av.x;
        As[acol4 + 1][arow] = av.y;
        As[acol4 + 2][arow] = av.z;
        As[acol4 + 3][arow] = av.w;

        float4 bv = *(const float4*)(W + (size_t)(kk + brow) * 128 + bcol4);
        *(float2*)&Bs[brow][bphys]     = make_float2(bv.x, bv.y);
        *(float2*)&Bs[brow][bphys + 2] = make_float2(bv.z, bv.w);
        __syncthreads();

#pragma unroll
        for (int k = 0; k < 8; k++) {
            float4 rm0 = *(const float4*)&As[k][tr * 8];
            float4 rm1 = *(const float4*)&As[k][tr * 8 + 4];
            ull rmd[8];
            rmd[0] = pack_dup(rm0.x); rmd[1] = pack_dup(rm0.y);
            rmd[2] = pack_dup(rm0.z); rmd[3] = pack_dup(rm0.w);
            rmd[4] = pack_dup(rm1.x); rmd[5] = pack_dup(rm1.y);
            rmd[6] = pack_dup(rm1.z); rmd[7] = pack_dup(rm1.w);

            const ull* bp = (const ull*)&Bs[k][tc * 10];  // 10 = 8 + 2 skew
            ull rn0 = bp[0], rn1 = bp[1], rn2 = bp[2], rn3 = bp[3];

#pragma unroll
            for (int i = 0; i < 8; i++) {
                fma2(acc[i][0], rmd[i], rn0);
                fma2(acc[i][1], rmd[i], rn1);
                fma2(acc[i][2], rmd[i], rn2);
                fma2(acc[i][3], rmd[i], rn3);
            }
        }
        __syncthreads();
    }

#pragma unroll
    for (int i = 0; i < 8; i++) {
        int gr = block_row + tr * 8 + i;
        if (gr < M) {
            float2 p0 = unpack2(acc[i][0]);
            float2 p1 = unpack2(acc[i][1]);
            float2 p2 = unpack2(acc[i][2]);
            float2 p3 = unpack2(acc[i][3]);
            __half2 h0 = __float22half2_rn(p0);
            __half2 h1 = __float22half2_rn(p1);
            __half2 h2v = __float22half2_rn(p2);
            __half2 h3 = __float22half2_rn(p3);
            uint4 val;
            val.x = *(unsigned*)&h0; val.y = *(unsigned*)&h1;
            val.z = *(unsigned*)&h2v; val.w = *(unsigned*)&h3;
            uint4* cp = (uint4*)(C + (size_t)gr * 128);
            cp[tc] = val;
        }
    }
}

// ---------------- SpMM: out(fp32) = bias + dis^2*h[n] + sum_e w_e*h[src_e] ----
// one warp per node; fp16 rows (256B), lane owns 4 channels (uint2 load).
__device__ __forceinline__ void acc4(float& x, float& y, float& z, float& w,
                                     float s, uint2 u) {
    __half2 p01 = *reinterpret_cast<__half2*>(&u.x);
    __half2 p23 = *reinterpret_cast<__half2*>(&u.y);
    float2 f01 = __half22float2(p01);
    float2 f23 = __half22float2(p23);
    x += s * f01.x; y += s * f01.y; z += s * f23.x; w += s * f23.y;
}

__global__ __launch_bounds__(256) void k_spmm(const __half* __restrict__ h,
                                              const float* __restrict__ bias,
                                              float* __restrict__ out, int do_relu) {
    int node = (blockIdx.x * blockDim.x + threadIdx.x) >> 5;
    if (node >= NN) return;
    int lane = threadIdx.x & 31;

    const uint2* h2p = (const uint2*)h;   // 8B per lane per row
    float dsi = g_dis[node];
    float sw  = dsi * dsi;

    float ax = 0.f, ay = 0.f, az = 0.f, aw = 0.f;
    float bx = 0.f, by = 0.f, bz = 0.f, bw = 0.f;
    acc4(ax, ay, az, aw, sw, h2p[node * 32 + lane]);

    int e   = g_off[node];
    int end = g_off[node + 1];

    for (; e + 3 < end; e += 4) {
        int2 e0 = g_epack[e];
        int2 e1 = g_epack[e + 1];
        int2 e2 = g_epack[e + 2];
        int2 e3 = g_epack[e + 3];
        uint2 v0 = h2p[e0.x * 32 + lane];
        uint2 v1 = h2p[e1.x * 32 + lane];
        uint2 v2 = h2p[e2.x * 32 + lane];
        uint2 v3 = h2p[e3.x * 32 + lane];
        acc4(ax, ay, az, aw, __int_as_float(e0.y), v0);
        acc4(bx, by, bz, bw, __int_as_float(e1.y), v1);
        acc4(ax, ay, az, aw, __int_as_float(e2.y), v2);
        acc4(bx, by, bz, bw, __int_as_float(e3.y), v3);
    }
    for (; e < end; e++) {
        int2 e0 = g_epack[e];
        acc4(ax, ay, az, aw, __int_as_float(e0.y), h2p[e0.x * 32 + lane]);
    }

    float4 bb = ((const float4*)bias)[lane];
    ax += bx + bb.x; ay += by + bb.y; az += bz + bb.z; aw += bw + bb.w;
    if (do_relu) {
        ax = fmaxf(ax, 0.f); ay = fmaxf(ay, 0.f);
        az = fmaxf(az, 0.f); aw = fmaxf(aw, 0.f);
    }
    ((float4*)out)[node * 32 + lane] = make_float4(ax, ay, az, aw);
}

// ---------------- launch ----------------
extern "C" void kernel_launch(void* const* d_in, const int* in_sizes, int n_in,
                              void* d_out, int out_size) {
    // metadata order: x, last_update, edge_index, t, msg, W1, b1, W2, b2
    const float* x  = (const float*)d_in[0];
    const int*   ei = (const int*)d_in[2];
    const float* W1 = (const float*)d_in[5];
    const float* b1 = (const float*)d_in[6];
    const float* W2 = (const float*)d_in[7];
    const float* b2 = (const float*)d_in[8];
    float* out = (float*)d_out;

    const int* src = ei;        // edge_index[0]
    const int* dst = ei + NE;   // edge_index[1]

    __half* h16;
    float*  agg;
    cudaGetSymbolAddress((void**)&h16, g_h16);
    cudaGetSymbolAddress((void**)&agg, g_agg);

    // CSR build
    k_init <<<(NN + 255) / 256, 256>>>();
    k_count<<<(NE + 255) / 256, 256>>>(dst);
    k_scanA<<<SCAN_NB, 256>>>();
    k_scanB<<<1, 256>>>();
    k_scanC<<<SCAN_NB, 256>>>();
    k_fill <<<(NE + 255) / 256, 256>>>(src, dst);

    // layer 1: h = x@W1 (fp16); agg+b1+relu (fp32)
    k_gemm<<<(NN + 127) / 128, 256>>>(x, W1, h16, NN);
    k_spmm<<<(NN * 32 + 255) / 256, 256>>>(h16, b1, agg, 1);

    // layer 2: h = agg@W2 (fp16); agg+b2 -> out (fp32)
    k_gemm<<<(NN + 127) / 128, 256>>>(agg, W2, h16, NN);
    k_spmm<<<(NN * 32 + 255) / 256, 256>>>(h16, b2, out, 0);
}